// round 9
// baseline (speedup 1.0000x reference)
#include <cuda_runtime.h>
#include <cuda_fp16.h>
#include <cstdint>

// ============================================================================
// GCN layer on GB300 (sm_103 base target):
//   fused:  blocks 0..511   : Qth = fp16( (H @ W)^T )   (unscaled, K-major)
//           blocks 512..8703: d = rowsum(A)^-1/2        (read-only pass over A)
//   spmm :  out = relu( d_m * sum_k (fp16(A[m,k]) * (fp16(d_k)*Qth[n,k])) )
//           A read as fp32 + converted in-reg; d-scaling folded into B-frags.
// ============================================================================

#define NROWS 8192
#define FDIM  256

__device__ float g_d[NROWS];
__device__ __align__(16) __half g_Qth[FDIM * NROWS];   // (HW)^T fp16 unscaled, 4MB

// ---------------- helpers ----------------
__device__ __forceinline__ uint32_t smem_u32(const void* p) {
    uint32_t a;
    asm("{ .reg .u64 t; cvta.to.shared.u64 t, %1; cvt.u32.u64 %0, t; }" : "=r"(a) : "l"(p));
    return a;
}
__device__ __forceinline__ uint64_t pack2dup(float v) {
    uint64_t r; asm("mov.b64 %0, {%1, %2};" : "=l"(r) : "f"(v), "f"(v)); return r;
}
__device__ __forceinline__ uint64_t fma2(uint64_t a, uint64_t b, uint64_t c) {
    uint64_t d; asm("fma.rn.f32x2 %0, %1, %2, %3;" : "=l"(d) : "l"(a), "l"(b), "l"(c)); return d;
}
__device__ __forceinline__ void unpack2(uint64_t v, float& lo, float& hi) {
    asm("mov.b64 {%0, %1}, %2;" : "=f"(lo), "=f"(hi) : "l"(v));
}

#define CP_ASYNC16(sdst, gsrc) \
    asm volatile("cp.async.cg.shared.global [%0], [%1], 16;" :: "r"(sdst), "l"(gsrc) : "memory")
#define CP_COMMIT() asm volatile("cp.async.commit_group;" ::: "memory")
#define CP_WAIT1()  asm volatile("cp.async.wait_group 1;" ::: "memory")

__device__ __forceinline__ uint32_t lds32(uint32_t p) {
    uint32_t v; asm volatile("ld.shared.b32 %0, [%1];" : "=r"(v) : "r"(p)); return v;
}
__device__ __forceinline__ float2 lds64f(uint32_t p) {
    float2 v; asm volatile("ld.shared.v2.f32 {%0, %1}, [%2];" : "=f"(v.x), "=f"(v.y) : "r"(p));
    return v;
}
__device__ __forceinline__ uint32_t cvt_h2(float2 v) {
    uint32_t r;
    asm("cvt.rn.f16x2.f32 %0, %1, %2;" : "=r"(r) : "f"(v.y), "f"(v.x));
    return r;
}
__device__ __forceinline__ uint32_t hmul2(uint32_t a, uint32_t b) {
    uint32_t r; asm("mul.f16x2 %0, %1, %2;" : "=r"(r) : "r"(a), "r"(b)); return r;
}

// ---------------------------------------------------------------------------
// Fused phase 1.
//   blocks [0, 512):  light GEMM 64x64 tile of Q = H@W, fp16 transposed store
//   blocks [512, ..): rowsum of A row (read-only), d = rsqrt(sum)
// ---------------------------------------------------------------------------
#define GEMM_BLOCKS 512   // (8192/64) * (256/64)
#define BKS 16

__global__ __launch_bounds__(256, 5) void fused_pre(const float* __restrict__ A,
                                                    const float* __restrict__ H,
                                                    const float* __restrict__ W,
                                                    float* __restrict__ d,
                                                    __half* __restrict__ Qth) {
    __shared__ float As[BKS][64];
    __shared__ float Bs[BKS][64];
    __shared__ float red[8];

    const int tid = threadIdx.x;

    if (blockIdx.x >= GEMM_BLOCKS) {
        // ---------------- rowsum only (no write-back of A) ----------------
        const int row = blockIdx.x - GEMM_BLOCKS;
        const float4* Ar = (const float4*)(A + (size_t)row * NROWS);
        float s = 0.f;
        #pragma unroll
        for (int i = 0; i < 8; i++) {
            float4 v = Ar[tid + 256 * i];
            s += (v.x + v.y) + (v.z + v.w);
        }
        #pragma unroll
        for (int o = 16; o; o >>= 1) s += __shfl_xor_sync(0xffffffffu, s, o);
        if ((tid & 31) == 0) red[tid >> 5] = s;
        __syncthreads();
        if (tid < 8) {
            s = red[tid];
            #pragma unroll
            for (int o = 4; o; o >>= 1) s += __shfl_xor_sync(0xffu, s, o);
            if (tid == 0) d[row] = rsqrtf(s);
        }
        return;
    }

    // ---------------- light GEMM: 64x64 tile, 4x4 per thread ----------------
    const int tx = tid & 15;            // n
    const int ty = tid >> 4;            // m
    const int bm = (int)(blockIdx.x >> 2) * 64;   // node rows of H
    const int bn = (int)(blockIdx.x & 3) * 64;    // feature cols

    const int arow = tid >> 2;          // 0..63
    const int acol = (tid & 3) << 2;    // 0,4,8,12
    const float* Ap = H + (size_t)(bm + arow) * FDIM + acol;
    const int brow = tid >> 4;          // 0..15
    const int bcol = (tid & 15) << 2;
    const float* Bp = W + (size_t)brow * FDIM + bn + bcol;

    uint64_t acc[2][4];
    #pragma unroll
    for (int i = 0; i < 2; i++)
        #pragma unroll
        for (int j = 0; j < 4; j++) acc[i][j] = 0ull;

    float4 pa = *(const float4*)(Ap);
    float4 pb = *(const float4*)(Bp);

    for (int kt = 0; kt < FDIM; kt += BKS) {
        As[acol + 0][arow] = pa.x; As[acol + 1][arow] = pa.y;
        As[acol + 2][arow] = pa.z; As[acol + 3][arow] = pa.w;
        *(float4*)&Bs[brow][bcol] = pb;
        __syncthreads();

        const int ktn = kt + BKS;
        if (ktn < FDIM) {
            pa = *(const float4*)(Ap + ktn);
            pb = *(const float4*)(Bp + (size_t)ktn * FDIM);
        }

        #pragma unroll
        for (int k = 0; k < BKS; k++) {
            const ulonglong2 av2 = *(const ulonglong2*)&As[k][ty * 4];
            const uint64_t av[2] = {av2.x, av2.y};
            const float4 bv = *(const float4*)&Bs[k][tx * 4];
            uint64_t bb[4];
            bb[0] = pack2dup(bv.x); bb[1] = pack2dup(bv.y);
            bb[2] = pack2dup(bv.z); bb[3] = pack2dup(bv.w);
            #pragma unroll
            for (int i = 0; i < 2; i++)
                #pragma unroll
                for (int j = 0; j < 4; j++)
                    acc[i][j] = fma2(av[i], bb[j], acc[i][j]);
        }
        __syncthreads();
    }

    // transposed fp16 store: Qth[col][bm+ty*4 .. +3]
    const int m0 = bm + ty * 4;
    #pragma unroll
    for (int j = 0; j < 4; j++) {
        const int col = bn + tx * 4 + j;
        float v[4];
        unpack2(acc[0][j], v[0], v[1]);
        unpack2(acc[1][j], v[2], v[3]);
        __half2 h0 = __floats2half2_rn(v[0], v[1]);
        __half2 h1 = __floats2half2_rn(v[2], v[3]);
        uint2 u;
        u.x = *(uint32_t*)&h0;
        u.y = *(uint32_t*)&h1;
        *(uint2*)(Qth + (size_t)col * NROWS + m0) = u;
    }
}

// ---------------------------------------------------------------------------
// spmm: out = relu( d_m * sum_k fp16(A[m,k]) * (fp16(d_k) * Qth[n,k]) )
// A fp32 staged via cp.async, converted in-reg; B fp16 staged; d fp32 in smem.
// Per CTA: M=128, N=128, K=8192.  NS=3 ring, KT=64.  2x4 warps of 64x32.
// ---------------------------------------------------------------------------
#define NS 3
#define KT 64
#define NITER (NROWS / KT)           // 128
#define ROWA 288                     // A row pad: 64 fp32 = 256B + 32B
#define ROWB2 144                    // B row pad: 64 fp16 = 128B + 16B
#define TILE_A (128 * ROWA)          // 36864
#define TILE_BB (128 * ROWB2)        // 18432
#define STG_B (TILE_A + TILE_BB)     // 55296
#define D_OFF (NS * STG_B)           // 165888
#define SMEM_BIG (D_OFF + NROWS * 4) // 198656

__global__ __launch_bounds__(256, 1) void spmm_mma(const float* __restrict__ A,
                                                   const __half* __restrict__ Qth,
                                                   const float* __restrict__ dvec,
                                                   float* __restrict__ out) {
    extern __shared__ char smem[];
    const uint32_t sb = smem_u32(smem);
    const int tid = threadIdx.x;
    const int lane = tid & 31;
    const int wid = tid >> 5;
    const int warp_m = wid >> 2;          // 0..1
    const int warp_n = wid & 3;           // 0..3
    const int bm = (int)blockIdx.y * 128;
    const int bn = (int)blockIdx.x * 128;

    // cp.async slots: A fp32 128x64f -> 8 x 16B/thread; B fp16 128x64h -> 4 x 16B
    uint32_t adst[8];
    const char* asrc[8];
    #pragma unroll
    for (int i = 0; i < 8; i++) {
        const int idx = tid + 256 * i;    // 0..2047
        const int r = idx >> 4, c = idx & 15;
        adst[i] = (uint32_t)(r * ROWA + c * 16);
        asrc[i] = (const char*)(A + (size_t)(bm + r) * NROWS) + c * 16;
    }
    uint32_t bdst[4];
    const char* bsrc[4];
    #pragma unroll
    for (int i = 0; i < 4; i++) {
        const int idx = tid + 256 * i;    // 0..1023
        const int r = idx >> 3, c = idx & 7;
        bdst[i] = (uint32_t)(TILE_A + r * ROWB2 + c * 16);
        bsrc[i] = (const char*)(Qth + (size_t)(bn + r) * NROWS) + c * 16;
    }

    auto load_stage = [&](int s, int it) {
        const uint32_t base = sb + s * STG_B;
        const size_t ka = (size_t)it * (KT * 4);   // A bytes per iter
        const size_t kb = (size_t)it * (KT * 2);   // B bytes per iter
        #pragma unroll
        for (int i = 0; i < 8; i++) CP_ASYNC16(base + adst[i], asrc[i] + ka);
        #pragma unroll
        for (int i = 0; i < 4; i++) CP_ASYNC16(base + bdst[i], bsrc[i] + kb);
    };

    float acc[4][4][4];
    #pragma unroll
    for (int mt = 0; mt < 4; mt++)
        #pragma unroll
        for (int nt = 0; nt < 4; nt++)
            #pragma unroll
            for (int q = 0; q < 4; q++) acc[mt][nt][q] = 0.f;

    // prologue: stages 0..NS-2
    #pragma unroll
    for (int j = 0; j < NS - 1; j++) { load_stage(j, j); CP_COMMIT(); }

    // d -> smem (fp32, all 8192)
    #pragma unroll
    for (int i = 0; i < 8; i++) {
        const int idx = tid + 256 * i;    // 0..2047 float4s
        float4 v = *(const float4*)(dvec + idx * 4);
        *(float4*)(smem + D_OFF + idx * 16) = v;
    }

    // lane base offsets
    const uint32_t a_lane = (uint32_t)((warp_m * 64 + (lane >> 2)) * ROWA + (lane & 3) * 8);
    const uint32_t b_lane = (uint32_t)(TILE_A + (warp_n * 32 + (lane >> 2)) * ROWB2 + (lane & 3) * 4);
    const uint32_t d_lane = (uint32_t)(D_OFF + (lane & 3) * 8);

    for (int it = 0; it < NITER; it++) {
        CP_WAIT1();                 // stage 'it' resident
        __syncthreads();            // readers of stage it-1 done; d smem visible

        const int j = it + NS - 1;
        if (j < NITER) load_stage(j % NS, j);
        CP_COMMIT();

        const uint32_t stage = sb + (it % NS) * STG_B;
        const uint32_t dbase = sb + d_lane + (uint32_t)(it * KT * 4);
        #pragma unroll
        for (int kc = 0; kc < 4; kc++) {
            // d scales for this kc: pairs (k, k+1) and (k+8, k+9)
            const uint32_t dk = dbase + kc * 64;
            const uint32_t dh0 = cvt_h2(lds64f(dk));
            const uint32_t dh1 = cvt_h2(lds64f(dk + 32));
            // A frags: fp32 pairs -> fp16x2
            uint32_t a[4][4];
            #pragma unroll
            for (int mt = 0; mt < 4; mt++) {
                const uint32_t p = stage + a_lane + mt * (16 * ROWA) + kc * 64;
                a[mt][0] = cvt_h2(lds64f(p));
                a[mt][1] = cvt_h2(lds64f(p + 8 * ROWA));
                a[mt][2] = cvt_h2(lds64f(p + 32));
                a[mt][3] = cvt_h2(lds64f(p + 8 * ROWA + 32));
            }
            // B frags: fp16, scaled by d
            uint32_t b[4][2];
            #pragma unroll
            for (int nt = 0; nt < 4; nt++) {
                const uint32_t p = stage + b_lane + nt * (8 * ROWB2) + kc * 32;
                b[nt][0] = hmul2(lds32(p), dh0);
                b[nt][1] = hmul2(lds32(p + 16), dh1);
            }
            #pragma unroll
            for (int mt = 0; mt < 4; mt++)
                #pragma unroll
                for (int nt = 0; nt < 4; nt++)
                    asm volatile(
                        "mma.sync.aligned.m16n8k16.row.col.f32.f16.f16.f32 "
                        "{%0,%1,%2,%3}, {%4,%5,%6,%7}, {%8,%9}, {%0,%1,%2,%3};"
                        : "+f"(acc[mt][nt][0]), "+f"(acc[mt][nt][1]),
                          "+f"(acc[mt][nt][2]), "+f"(acc[mt][nt][3])
                        : "r"(a[mt][0]), "r"(a[mt][1]), "r"(a[mt][2]), "r"(a[mt][3]),
                          "r"(b[nt][0]), "r"(b[nt][1]));
        }
    }

    // epilogue: row scale from smem d, relu, float2 stores
    #pragma unroll
    for (int mt = 0; mt < 4; mt++) {
        const int r0 = bm + warp_m * 64 + mt * 16 + (lane >> 2);
        const float s0 = *(const float*)(smem + D_OFF + r0 * 4);
        const float s1 = *(const float*)(smem + D_OFF + (r0 + 8) * 4);
        #pragma unroll
        for (int nt = 0; nt < 4; nt++) {
            const int col = bn + warp_n * 32 + nt * 8 + (lane & 3) * 2;
            float2 v0, v1;
            v0.x = fmaxf(s0 * acc[mt][nt][0], 0.f);
            v0.y = fmaxf(s0 * acc[mt][nt][1], 0.f);
            v1.x = fmaxf(s1 * acc[mt][nt][2], 0.f);
            v1.y = fmaxf(s1 * acc[mt][nt][3], 0.f);
            *(float2*)(out + (size_t)r0 * FDIM + col)       = v0;
            *(float2*)(out + (size_t)(r0 + 8) * FDIM + col) = v1;
        }
    }
}

// ---------------------------------------------------------------------------
extern "C" void kernel_launch(void* const* d_in, const int* in_sizes, int n_in,
                              void* d_out, int out_size) {
    const float* H = nullptr;
    const float* A = nullptr;
    const float* W = nullptr;
    for (int i = 0; i < n_in; i++) {
        if (in_sizes[i] == NROWS * NROWS) A = (const float*)d_in[i];
        else if (in_sizes[i] == FDIM * FDIM) W = (const float*)d_in[i];
        else if (in_sizes[i] == NROWS * FDIM) H = (const float*)d_in[i];
    }
    float* out = (float*)d_out;

    float* dptr = nullptr;
    __half* Qtp = nullptr;
    cudaGetSymbolAddress((void**)&dptr, g_d);
    cudaGetSymbolAddress((void**)&Qtp, g_Qth);

    cudaFuncSetAttribute(spmm_mma, cudaFuncAttributeMaxDynamicSharedMemorySize, SMEM_BIG);

    // 1) fused: Qth = fp16((H@W)^T) (unscaled)  ||  d = rowsum(A)^-1/2
    fused_pre<<<GEMM_BLOCKS + NROWS, 256>>>(A, H, W, dptr, Qtp);

    // 2) out = relu(d_m * (A @ diag(d) Q))  via mma.sync fp16, fp32-A in-reg cvt
    dim3 gridB(2, NROWS / 128);
    spmm_mma<<<gridB, 256, SMEM_BIG>>>(A, Qtp, dptr, out);
}

// round 10
// speedup vs baseline: 1.0779x; 1.0779x over previous
#include <cuda_runtime.h>
#include <cuda_fp16.h>
#include <cstdint>

// ============================================================================
// GCN layer on GB300 (sm_103 base target):
//   fused:  blocks 0..511   : Qth = fp16( (H @ W)^T )  (unscaled, K-major)
//           blocks 512..8703: d = rowsum(A)^-1/2, Ah = fp16(A)
//   spmm :  out = relu( d_m * sum_k Ah[m,k] * (fp16(d_k) * Qth[n,k]) )
//           (R5-proven fp16 fragment path; d-scaling folded into B frags)
// ============================================================================

#define NROWS 8192
#define FDIM  256

__device__ float g_d[NROWS];
__device__ __align__(16) __half g_Ah[(size_t)NROWS * NROWS];   // fp16 A, 128MB
__device__ __align__(16) __half g_Qth[FDIM * NROWS];           // (HW)^T fp16, 4MB

// ---------------- helpers ----------------
__device__ __forceinline__ uint32_t smem_u32(const void* p) {
    uint32_t a;
    asm("{ .reg .u64 t; cvta.to.shared.u64 t, %1; cvt.u32.u64 %0, t; }" : "=r"(a) : "l"(p));
    return a;
}
__device__ __forceinline__ uint64_t pack2dup(float v) {
    uint64_t r; asm("mov.b64 %0, {%1, %2};" : "=l"(r) : "f"(v), "f"(v)); return r;
}
__device__ __forceinline__ uint64_t fma2(uint64_t a, uint64_t b, uint64_t c) {
    uint64_t d; asm("fma.rn.f32x2 %0, %1, %2, %3;" : "=l"(d) : "l"(a), "l"(b), "l"(c)); return d;
}
__device__ __forceinline__ void unpack2(uint64_t v, float& lo, float& hi) {
    asm("mov.b64 {%0, %1}, %2;" : "=f"(lo), "=f"(hi) : "l"(v));
}

#define CP_ASYNC16(sdst, gsrc) \
    asm volatile("cp.async.cg.shared.global [%0], [%1], 16;" :: "r"(sdst), "l"(gsrc) : "memory")
#define CP_COMMIT() asm volatile("cp.async.commit_group;" ::: "memory")
#define CP_WAIT3()  asm volatile("cp.async.wait_group 3;" ::: "memory")

__device__ __forceinline__ uint32_t lds32(uint32_t p) {
    uint32_t v; asm volatile("ld.shared.b32 %0, [%1];" : "=r"(v) : "r"(p)); return v;
}
__device__ __forceinline__ float2 lds64f(uint32_t p) {
    float2 v; asm volatile("ld.shared.v2.f32 {%0, %1}, [%2];" : "=f"(v.x), "=f"(v.y) : "r"(p));
    return v;
}
__device__ __forceinline__ uint32_t cvt_h2(float2 v) {
    uint32_t r;
    asm("cvt.rn.f16x2.f32 %0, %1, %2;" : "=r"(r) : "f"(v.y), "f"(v.x));
    return r;
}
__device__ __forceinline__ uint32_t hmul2(uint32_t a, uint32_t b) {
    uint32_t r; asm("mul.f16x2 %0, %1, %2;" : "=r"(r) : "r"(a), "r"(b)); return r;
}

// ---------------------------------------------------------------------------
// Fused phase 1.
//   blocks [0, 512):   64x64 GEMM tile of Q = H@W, fp16 transposed store
//   blocks [512, ..):  rowsum of A row + fp16 convert (Ah)
// launch_bounds(256,5) caps regs (~51) so the rowsum wave keeps occupancy.
// ---------------------------------------------------------------------------
#define GEMM_BLOCKS 512   // (8192/64) * (256/64)
#define BKS 16

__global__ __launch_bounds__(256, 5) void fused_pre(const float* __restrict__ A,
                                                    const float* __restrict__ H,
                                                    const float* __restrict__ W,
                                                    float* __restrict__ d,
                                                    __half* __restrict__ Ah,
                                                    __half* __restrict__ Qth) {
    __shared__ float As[BKS][64];
    __shared__ float Bs[BKS][64];
    __shared__ float red[8];

    const int tid = threadIdx.x;

    if (blockIdx.x >= GEMM_BLOCKS) {
        // ---------------- rowsum + fp16 convert ----------------
        const int row = blockIdx.x - GEMM_BLOCKS;
        const float4* Ar = (const float4*)(A + (size_t)row * NROWS);
        uint2* Hr = (uint2*)(Ah + (size_t)row * NROWS);
        float s = 0.f;
        #pragma unroll
        for (int i = 0; i < 8; i++) {
            const int idx = tid + 256 * i;
            float4 v = Ar[idx];
            s += (v.x + v.y) + (v.z + v.w);
            __half2 h01 = __floats2half2_rn(v.x, v.y);
            __half2 h23 = __floats2half2_rn(v.z, v.w);
            uint2 u;
            u.x = *(uint32_t*)&h01;
            u.y = *(uint32_t*)&h23;
            Hr[idx] = u;
        }
        #pragma unroll
        for (int o = 16; o; o >>= 1) s += __shfl_xor_sync(0xffffffffu, s, o);
        if ((tid & 31) == 0) red[tid >> 5] = s;
        __syncthreads();
        if (tid < 8) {
            s = red[tid];
            #pragma unroll
            for (int o = 4; o; o >>= 1) s += __shfl_xor_sync(0xffu, s, o);
            if (tid == 0) d[row] = rsqrtf(s);
        }
        return;
    }

    // ---------------- light GEMM: 64x64 tile, 4x4 per thread ----------------
    const int tx = tid & 15;
    const int ty = tid >> 4;
    const int bm = (int)(blockIdx.x >> 2) * 64;   // node rows of H
    const int bn = (int)(blockIdx.x & 3) * 64;    // feature cols

    const int arow = tid >> 2;          // 0..63
    const int acol = (tid & 3) << 2;    // 0,4,8,12
    const float* Ap = H + (size_t)(bm + arow) * FDIM + acol;
    const int brow = tid >> 4;          // 0..15
    const int bcol = (tid & 15) << 2;
    const float* Bp = W + (size_t)brow * FDIM + bn + bcol;

    uint64_t acc[2][4];
    #pragma unroll
    for (int i = 0; i < 2; i++)
        #pragma unroll
        for (int j = 0; j < 4; j++) acc[i][j] = 0ull;

    float4 pa = *(const float4*)(Ap);
    float4 pb = *(const float4*)(Bp);

    for (int kt = 0; kt < FDIM; kt += BKS) {
        As[acol + 0][arow] = pa.x; As[acol + 1][arow] = pa.y;
        As[acol + 2][arow] = pa.z; As[acol + 3][arow] = pa.w;
        *(float4*)&Bs[brow][bcol] = pb;
        __syncthreads();

        const int ktn = kt + BKS;
        if (ktn < FDIM) {
            pa = *(const float4*)(Ap + ktn);
            pb = *(const float4*)(Bp + (size_t)ktn * FDIM);
        }

        #pragma unroll
        for (int k = 0; k < BKS; k++) {
            const ulonglong2 av2 = *(const ulonglong2*)&As[k][ty * 4];
            const uint64_t av[2] = {av2.x, av2.y};
            const float4 bv = *(const float4*)&Bs[k][tx * 4];
            uint64_t bb[4];
            bb[0] = pack2dup(bv.x); bb[1] = pack2dup(bv.y);
            bb[2] = pack2dup(bv.z); bb[3] = pack2dup(bv.w);
            #pragma unroll
            for (int i = 0; i < 2; i++)
                #pragma unroll
                for (int j = 0; j < 4; j++)
                    acc[i][j] = fma2(av[i], bb[j], acc[i][j]);
        }
        __syncthreads();
    }

    // transposed fp16 store: Qth[col][bm+ty*4 .. +3]
    const int m0 = bm + ty * 4;
    #pragma unroll
    for (int j = 0; j < 4; j++) {
        const int col = bn + tx * 4 + j;
        float v[4];
        unpack2(acc[0][j], v[0], v[1]);
        unpack2(acc[1][j], v[2], v[3]);
        __half2 h0 = __floats2half2_rn(v[0], v[1]);
        __half2 h1 = __floats2half2_rn(v[2], v[3]);
        uint2 u;
        u.x = *(uint32_t*)&h0;
        u.y = *(uint32_t*)&h1;
        *(uint2*)(Qth + (size_t)col * NROWS + m0) = u;
    }
}

// ---------------------------------------------------------------------------
// spmm (R5-proven shape): out = relu( d_m * sum_k Ah[m,k] * (d_k * Qth[n,k]) )
// Per CTA: M=128, N=128, K=8192. 2x4 warps of 64x32.  NS=5 ring, KT=64 halves.
// Rows padded to 144B (bank-clean).  d fp32 cached in smem; B frags scaled by
// fp16(d_k) via mul.f16x2 (hidden under HMMA).
// ---------------------------------------------------------------------------
#define NS 5
#define KT 64
#define NITER (NROWS / KT)            // 128
#define ROWB 144
#define TILE_B (128 * ROWB)           // 18432
#define STG_B (2 * TILE_B)            // 36864
#define D_OFF (NS * STG_B)            // 184320
#define SMEM_BIG (D_OFF + NROWS * 4)  // 217088

__global__ __launch_bounds__(256, 1) void spmm_mma(const __half* __restrict__ Ah,
                                                   const __half* __restrict__ Qth,
                                                   const float* __restrict__ dvec,
                                                   float* __restrict__ out) {
    extern __shared__ char smem[];
    const uint32_t sb = smem_u32(smem);
    const int tid = threadIdx.x;
    const int lane = tid & 31;
    const int wid = tid >> 5;
    const int warp_m = wid >> 2;          // 0..1
    const int warp_n = wid & 3;           // 0..3
    const int bm = (int)blockIdx.y * 128;
    const int bn = (int)blockIdx.x * 128;

    uint32_t dst[4];
    const char* asrc[4];
    const char* bsrc[4];
    #pragma unroll
    for (int i = 0; i < 4; i++) {
        const int idx = tid + 256 * i;
        const int r = idx >> 3, c = idx & 7;
        dst[i] = (uint32_t)(r * ROWB + c * 16);
        asrc[i] = (const char*)(Ah  + (size_t)(bm + r) * NROWS) + c * 16;
        bsrc[i] = (const char*)(Qth + (size_t)(bn + r) * NROWS) + c * 16;
    }

    auto load_stage = [&](int s, int it) {
        const uint32_t base = sb + s * STG_B;
        const size_t koff = (size_t)it * (KT * 2);
        #pragma unroll
        for (int i = 0; i < 4; i++) CP_ASYNC16(base + dst[i], asrc[i] + koff);
        #pragma unroll
        for (int i = 0; i < 4; i++) CP_ASYNC16(base + TILE_B + dst[i], bsrc[i] + koff);
    };

    float acc[4][4][4];
    #pragma unroll
    for (int mt = 0; mt < 4; mt++)
        #pragma unroll
        for (int nt = 0; nt < 4; nt++)
            #pragma unroll
            for (int q = 0; q < 4; q++) acc[mt][nt][q] = 0.f;

    // prologue: stages 0..NS-2
    #pragma unroll
    for (int j = 0; j < NS - 1; j++) { load_stage(j, j); CP_COMMIT(); }

    // d -> smem (fp32, all 8192); visible after iter-0 __syncthreads
    #pragma unroll
    for (int i = 0; i < 8; i++) {
        const int idx = tid + 256 * i;
        float4 v = *(const float4*)(dvec + idx * 4);
        *(float4*)(smem + D_OFF + idx * 16) = v;
    }

    const uint32_t a_lane_off = (uint32_t)((warp_m * 64 + (lane >> 2)) * ROWB + (lane & 3) * 4);
    const uint32_t b_lane_off = (uint32_t)(TILE_B + (warp_n * 32 + (lane >> 2)) * ROWB + (lane & 3) * 4);
    const uint32_t d_lane = (uint32_t)(D_OFF + (lane & 3) * 8);

    for (int it = 0; it < NITER; it++) {
        CP_WAIT3();
        __syncthreads();

        const int j = it + NS - 1;
        if (j < NITER) load_stage(j % NS, j);
        CP_COMMIT();

        const uint32_t stage = sb + (it % NS) * STG_B;
        const uint32_t dbase = sb + d_lane + (uint32_t)(it * KT * 4);
        #pragma unroll
        for (int kc = 0; kc < 4; kc++) {
            const uint32_t kb = (uint32_t)(kc * 32);
            // d scales: k-pairs (2*(lane&3), +1) and (+8, +9) within this kc
            const uint32_t dk = dbase + kc * 64;
            const uint32_t dh0 = cvt_h2(lds64f(dk));
            const uint32_t dh1 = cvt_h2(lds64f(dk + 32));
            uint32_t a[4][4];
            #pragma unroll
            for (int mt = 0; mt < 4; mt++) {
                const uint32_t p = stage + a_lane_off + mt * (16 * ROWB) + kb;
                a[mt][0] = lds32(p);
                a[mt][1] = lds32(p + 8 * ROWB);
                a[mt][2] = lds32(p + 16);
                a[mt][3] = lds32(p + 8 * ROWB + 16);
            }
            uint32_t b[4][2];
            #pragma unroll
            for (int nt = 0; nt < 4; nt++) {
                const uint32_t p = stage + b_lane_off + nt * (8 * ROWB) + kb;
                b[nt][0] = hmul2(lds32(p), dh0);
                b[nt][1] = hmul2(lds32(p + 16), dh1);
            }
            #pragma unroll
            for (int mt = 0; mt < 4; mt++)
                #pragma unroll
                for (int nt = 0; nt < 4; nt++)
                    asm volatile(
                        "mma.sync.aligned.m16n8k16.row.col.f32.f16.f16.f32 "
                        "{%0,%1,%2,%3}, {%4,%5,%6,%7}, {%8,%9}, {%0,%1,%2,%3};"
                        : "+f"(acc[mt][nt][0]), "+f"(acc[mt][nt][1]),
                          "+f"(acc[mt][nt][2]), "+f"(acc[mt][nt][3])
                        : "r"(a[mt][0]), "r"(a[mt][1]), "r"(a[mt][2]), "r"(a[mt][3]),
                          "r"(b[nt][0]), "r"(b[nt][1]));
        }
    }

    // epilogue: row scale from smem d, relu, float2 stores
    #pragma unroll
    for (int mt = 0; mt < 4; mt++) {
        const int r0 = bm + warp_m * 64 + mt * 16 + (lane >> 2);
        const float s0 = *(const float*)(smem + D_OFF + r0 * 4);
        const float s1 = *(const float*)(smem + D_OFF + (r0 + 8) * 4);
        #pragma unroll
        for (int nt = 0; nt < 4; nt++) {
            const int col = bn + warp_n * 32 + nt * 8 + (lane & 3) * 2;
            float2 v0, v1;
            v0.x = fmaxf(s0 * acc[mt][nt][0], 0.f);
            v0.y = fmaxf(s0 * acc[mt][nt][1], 0.f);
            v1.x = fmaxf(s1 * acc[mt][nt][2], 0.f);
            v1.y = fmaxf(s1 * acc[mt][nt][3], 0.f);
            *(float2*)(out + (size_t)r0 * FDIM + col)       = v0;
            *(float2*)(out + (size_t)(r0 + 8) * FDIM + col) = v1;
        }
    }
}

// ---------------------------------------------------------------------------
extern "C" void kernel_launch(void* const* d_in, const int* in_sizes, int n_in,
                              void* d_out, int out_size) {
    const float* H = nullptr;
    const float* A = nullptr;
    const float* W = nullptr;
    for (int i = 0; i < n_in; i++) {
        if (in_sizes[i] == NROWS * NROWS) A = (const float*)d_in[i];
        else if (in_sizes[i] == FDIM * FDIM) W = (const float*)d_in[i];
        else if (in_sizes[i] == NROWS * FDIM) H = (const float*)d_in[i];
    }
    float* out = (float*)d_out;

    float* dptr = nullptr;
    __half* Ahp = nullptr;
    __half* Qtp = nullptr;
    cudaGetSymbolAddress((void**)&dptr, g_d);
    cudaGetSymbolAddress((void**)&Ahp, g_Ah);
    cudaGetSymbolAddress((void**)&Qtp, g_Qth);

    cudaFuncSetAttribute(spmm_mma, cudaFuncAttributeMaxDynamicSharedMemorySize, SMEM_BIG);

    // 1) fused: Qth = fp16((H@W)^T)  ||  d = rowsum(A)^-1/2, Ah = fp16(A)
    fused_pre<<<GEMM_BLOCKS + NROWS, 256>>>(A, H, W, dptr, Ahp, Qtp);

    // 2) out = relu(d_m * (Ah @ diag(d) Q))  via mma.sync fp16
    dim3 gridB(2, NROWS / 128);
    spmm_mma<<<gridB, 256, SMEM_BIG>>>(Ahp, Qtp, dptr, out);
}